// round 12
// baseline (speedup 1.0000x reference)
#include <cuda_runtime.h>
#include <cuda_fp16.h>
#include <cstdint>

#define WSIZE 9216
#define PSTRIDE 9248

#define XPITCH 20                        // words/pixel: 16 data + 4 pad (conflict-free, proven R5)
#define XROWW  (130 * XPITCH)            // 2600
#define XT_WORDS (6 * XROWW)             // 15600
#define WPITCH 148                       // words/filter: 144 data + 4 pad (proven R5)
#define WT_WORDS (32 * WPITCH)           // 4736
#define SMEM_BYTES ((XT_WORDS + WT_WORDS) * 4)   // 81344 -> 2 CTAs/SM

__device__ __forceinline__ uint32_t pack2(float a, float b) {
    __half2 h = __floats2half2_rn(a, b);
    return *(uint32_t*)&h;
}
__device__ __forceinline__ void mma_f16(float& c0, float& c1, float& c2, float& c3,
                                        uint32_t a0, uint32_t a1, uint32_t a2, uint32_t a3,
                                        uint32_t b0, uint32_t b1) {
    asm volatile(
        "mma.sync.aligned.m16n8k16.row.col.f32.f16.f16.f32 "
        "{%0,%1,%2,%3}, {%4,%5,%6,%7}, {%8,%9}, {%0,%1,%2,%3};"
        : "+f"(c0), "+f"(c1), "+f"(c2), "+f"(c3)
        : "r"(a0), "r"(a1), "r"(a2), "r"(a3), "r"(b0), "r"(b1));
}

__global__ __launch_bounds__(256, 2)
void conv_mma_f16(const float* __restrict__ x, const float* __restrict__ params,
                  float* __restrict__ out) {
    extern __shared__ uint32_t smem[];
    uint32_t* sX = smem;                 // [row 0..5][pix 0..129][XPITCH], fp16 k-major
    uint32_t* sW = smem + XT_WORDS;      // [f][WPITCH], fp16 k-major

    const int tid = threadIdx.x;
    const int wid = tid >> 5;
    const int lid = tid & 31;
    const int g   = lid >> 2;
    const int t   = lid & 3;
    const int y0  = blockIdx.x * 4;      // 4 output rows per CTA
    const int b   = blockIdx.y;

    const float* pw = params + (long)b * PSTRIDE;

    // ---- stage raw W [k][f] into the (not yet used) X region, pitch 33 ----
    {
        float* sF = (float*)sX;
        #pragma unroll
        for (int it = 0; it < 36; it++) {
            int i = tid + it * 256;      // 0..9215
            int k = i >> 5, f = i & 31;
            sF[k * 33 + f] = pw[i];      // coalesced LDG; banks (k+f)%32 distinct -> no conflict
        }
    }
    __syncthreads();

    // ---- transpose + fp16-convert into sW[f][WPITCH] ----
    {
        const float* sF = (const float*)sX;
        #pragma unroll
        for (int it = 0; it < 18; it++) {
            int i = tid + it * 256;      // 0..4607
            int f = i / 144, n = i - f * 144;
            sW[f * WPITCH + n] = pack2(sF[(2 * n) * 33 + f], sF[(2 * n + 1) * 33 + f]);
        }
    }
    __syncthreads();

    // ---- build X tile (overwrites staging): rows y0-1..y0+4, pixels -1..128 at 0..129 ----
    const float* xb = x + (long)b * (128 * 128 * 32);
    #pragma unroll
    for (int it = 0; it < 24; it++) {
        int idx = tid + it * 256;        // 0..6143
        int c4  = idx & 7;
        int px  = (idx >> 3) & 127;
        int row = idx >> 10;             // 0..5
        int gy  = y0 + row - 1;
        uint2 v = make_uint2(0u, 0u);
        if ((unsigned)gy < 128u) {
            float4 s = *(const float4*)(xb + ((gy * 128 + px) * 32 + c4 * 4));
            v.x = pack2(s.x, s.y);
            v.y = pack2(s.z, s.w);
        }
        *(uint2*)(sX + row * XROWW + (px + 1) * XPITCH + c4 * 2) = v;
    }
    if (tid < 192) {
        int row = tid >> 5, rem = tid & 31;
        int pix = (rem >> 4) ? 129 : 0;
        sX[row * XROWW + pix * XPITCH + (rem & 15)] = 0u;
    }
    __syncthreads();

    const int yl = wid >> 1;             // local output row 0..3
    const int m0 = (wid & 1) * 64;       // 64 px per warp

    float acc[4][4][4];
    #pragma unroll
    for (int mi = 0; mi < 4; mi++)
        #pragma unroll
        for (int nt = 0; nt < 4; nt++)
            #pragma unroll
            for (int j = 0; j < 4; j++) acc[mi][nt][j] = 0.f;

    #pragma unroll
    for (int kh = 0; kh < 3; kh++) {
        const uint32_t* xr = sX + (yl + kh) * XROWW;
        #pragma unroll
        for (int kw = 0; kw < 3; kw++) {
            #pragma unroll
            for (int c16 = 0; c16 < 2; c16++) {
                const int k0w = kh * 48 + kw * 16 + c16 * 8;

                // B fragments (scalar LDS, proven conflict-free)
                uint32_t b0[4], b1[4];
                const uint32_t* wp = sW + k0w + t;
                #pragma unroll
                for (int nt = 0; nt < 4; nt++) {
                    int f = nt * 8 + g;
                    b0[nt] = wp[f * WPITCH];
                    b1[nt] = wp[f * WPITCH + 4];
                }

                #pragma unroll
                for (int mi = 0; mi < 4; mi++) {
                    const uint32_t* ap = xr + (m0 + mi * 16 + g + kw) * XPITCH
                                            + c16 * 8 + t;
                    uint32_t a0 = ap[0];
                    uint32_t a1 = ap[8 * XPITCH];
                    uint32_t a2 = ap[4];
                    uint32_t a3 = ap[8 * XPITCH + 4];
                    #pragma unroll
                    for (int nt = 0; nt < 4; nt++)
                        mma_f16(acc[mi][nt][0], acc[mi][nt][1],
                                acc[mi][nt][2], acc[mi][nt][3],
                                a0, a1, a2, a3, b0[nt], b1[nt]);
                }
            }
        }
    }

    // ---- epilogue: + bias, direct STG (R5-proven) ----
    const float* bp = pw + WSIZE;
    float* ob = out + ((long)(b * 128 + y0 + yl)) * 128 * 32;
    #pragma unroll
    for (int nt = 0; nt < 4; nt++) {
        int f = nt * 8 + t * 2;
        float2 bias = *(const float2*)(bp + f);
        #pragma unroll
        for (int mi = 0; mi < 4; mi++) {
            int px = m0 + mi * 16 + g;
            float2 o0, o1;
            o0.x = acc[mi][nt][0] + bias.x;
            o0.y = acc[mi][nt][1] + bias.y;
            o1.x = acc[mi][nt][2] + bias.x;
            o1.y = acc[mi][nt][3] + bias.y;
            *(float2*)(ob + px * 32 + f)       = o0;
            *(float2*)(ob + (px + 8) * 32 + f) = o1;
        }
    }
}

extern "C" void kernel_launch(void* const* d_in, const int* in_sizes, int n_in,
                              void* d_out, int out_size) {
    const float* x      = (const float*)d_in[0];
    const float* params = (const float*)d_in[1];
    float* out          = (float*)d_out;

    cudaFuncSetAttribute(conv_mma_f16, cudaFuncAttributeMaxDynamicSharedMemorySize, SMEM_BYTES);
    dim3 grid(32, 32);   // (row-quad, batch)
    conv_mma_f16<<<grid, 256, SMEM_BYTES>>>(x, params, out);
}